// round 14
// baseline (speedup 1.0000x reference)
#include <cuda_runtime.h>
#include <cuda_bf16.h>
#include <cstdint>

#define SEQ 2048
#define HD  64
#define OUT_ELEMS (16*SEQ*HD)

__device__ float g_rowsum[16 * SEQ];

// ---------------- helpers ----------------
__device__ __forceinline__ uint32_t smem_u32(const void* p) {
    uint32_t a;
    asm("{ .reg .u64 t; cvta.to.shared.u64 t, %1; cvt.u32.u64 %0, t; }" : "=r"(a) : "l"(p));
    return a;
}

#define LDSM4(r, a) \
    asm volatile("ldmatrix.sync.aligned.m8n8.x4.shared.b16 {%0,%1,%2,%3}, [%4];" \
        : "=r"((r)[0]), "=r"((r)[1]), "=r"((r)[2]), "=r"((r)[3]) : "r"(a))
#define LDSM2(r, a) \
    asm volatile("ldmatrix.sync.aligned.m8n8.x2.shared.b16 {%0,%1}, [%2];" \
        : "=r"((r)[0]), "=r"((r)[1]) : "r"(a))
#define LDSM4T(r, a) \
    asm volatile("ldmatrix.sync.aligned.m8n8.x4.trans.shared.b16 {%0,%1,%2,%3}, [%4];" \
        : "=r"((r)[0]), "=r"((r)[1]), "=r"((r)[2]), "=r"((r)[3]) : "r"(a))

__device__ __forceinline__ void mma16816(float* d, const uint32_t* a, const uint32_t* b) {
    asm volatile(
        "mma.sync.aligned.m16n8k16.row.col.f32.bf16.bf16.f32 "
        "{%0,%1,%2,%3}, {%4,%5,%6,%7}, {%8,%9}, {%0,%1,%2,%3};"
        : "+f"(d[0]), "+f"(d[1]), "+f"(d[2]), "+f"(d[3])
        : "r"(a[0]), "r"(a[1]), "r"(a[2]), "r"(a[3]), "r"(b[0]), "r"(b[1]));
}

// fast 2^t : FFMA-only. |t| < 60 assumed.
__device__ __forceinline__ float fexp2(float t) {
    float z = t + 12582912.0f;
    int   i = __float_as_int(z);
    float f = t - (z - 12582912.0f);
    float p =          1.33335581e-3f;
    p = fmaf(p, f, 9.61812910e-3f);
    p = fmaf(p, f, 5.55041087e-2f);
    p = fmaf(p, f, 2.40226507e-1f);
    p = fmaf(p, f, 6.93147180e-1f);
    p = fmaf(p, f, 1.0f);
    float sc = __int_as_float((i + 127) << 23);
    return p * sc;
}
#define EXSCL 0.18033688011f   // 0.125 * log2(e)

// bf16 tiles: 64 elems (128B) per row, 16B-chunk xor swizzle
#define SW(o) ((o) ^ (((o) >> 3) & 0x70))
__device__ __forceinline__ uint32_t swz(uint32_t base, int row, int chunk) {
    return base + row * 128 + (((chunk ^ (row & 7)) & 7) << 4);
}

// split f32x4 -> bf16 hi/lo, 2x STS.64 (off % 8 == 0 so SW(off+4)==SW(off)+4)
__device__ __forceinline__ void store_split4(float4 v, char* hb, char* lb, int off) {
    __nv_bfloat162 h0 = __floats2bfloat162_rn(v.x, v.y);
    __nv_bfloat162 h1 = __floats2bfloat162_rn(v.z, v.w);
    float2 f0 = __bfloat1622float2(h0), f1 = __bfloat1622float2(h1);
    __nv_bfloat162 l0 = __floats2bfloat162_rn(v.x - f0.x, v.y - f0.y);
    __nv_bfloat162 l1 = __floats2bfloat162_rn(v.z - f1.x, v.w - f1.y);
    int s0 = SW(off);
    uint2 hp = make_uint2(reinterpret_cast<uint32_t&>(h0), reinterpret_cast<uint32_t&>(h1));
    uint2 lp = make_uint2(reinterpret_cast<uint32_t&>(l0), reinterpret_cast<uint32_t&>(l1));
    *(uint2*)(hb + s0) = hp;
    *(uint2*)(lb + s0) = lp;
}

// split f32 pair -> bf16 hi/lo, two STS.32 (for fragment epilogue -> E smem tile)
__device__ __forceinline__ void store_split2(float x, float y, char* hb, char* lb, int off) {
    __nv_bfloat162 h = __floats2bfloat162_rn(x, y);
    float2 f = __bfloat1622float2(h);
    __nv_bfloat162 l = __floats2bfloat162_rn(x - f.x, y - f.y);
    int s0 = SW(off);
    *(uint32_t*)(hb + s0) = reinterpret_cast<uint32_t&>(h);
    *(uint32_t*)(lb + s0) = reinterpret_cast<uint32_t&>(l);
}

// -------- Fused kernel: per 64-k tile: S-MMA -> exp epilogue -> PV-MMA --------
// smem: QH 8K | QL 8K | K stages 2x16K | V stages 2x16K | EH 8K | EL 8K | rs
#define A_QH 0
#define A_QL 8192
#define A_KH(s) (16384 + (s)*16384)
#define A_KL(s) (16384 + (s)*16384 + 8192)
#define A_VH(s) (49152 + (s)*16384)
#define A_VL(s) (49152 + (s)*16384 + 8192)
#define A_EH 81920
#define A_EL 90112
#define A_RS 98304
#define A_SZ (A_RS + 768)

__global__ void __launch_bounds__(256, 2) attn_k(
    const float* __restrict__ Q, const float* __restrict__ Kg,
    const float* __restrict__ Vg,
    const int* __restrict__ Mk, const float* __restrict__ P,
    float* __restrict__ E, float* __restrict__ O)
{
    extern __shared__ char sm[];
    const uint32_t sb = smem_u32(sm);
    const int t = threadIdx.x, w = t >> 5, lane = t & 31;
    const int mw = w >> 1, nw = w & 1;     // warp: q-rows mw*16, k/d-cols nw*32
    const int bh = blockIdx.y, q0 = blockIdx.x * 64;

    const float* Qb = Q + ((size_t)bh * SEQ + q0) * HD;
    const float* Kb = Kg + (size_t)bh * SEQ * HD;
    const float* Vb = Vg + (size_t)bh * SEQ * HD;

    // resident Q (64 x 64) split to smem
#pragma unroll
    for (int i = 0; i < 4; i++) {
        int idx = t + i * 256, r = idx >> 4, c = idx & 15;
        store_split4(*(const float4*)(Qb + r * HD + c * 4), sm + A_QH, sm + A_QL, r * 128 + c * 8);
    }

    // prefetch K/V tile 0 (64 rows x 64 cols each)
    const int lr = t >> 4, lc = t & 15;
    float4 kr[4], vr[4];
#pragma unroll
    for (int i = 0; i < 4; i++) {
        kr[i] = *(const float4*)(Kb + (size_t)(lr + i * 16) * HD + lc * 4);
        vr[i] = *(const float4*)(Vb + (size_t)(lr + i * 16) * HD + lc * 4);
    }

    float rs0 = 0.0f, rs1 = 0.0f;
    const int fr = lane >> 2;
    const int fc = 2 * (lane & 3);

    float acc_o[4][4];
#pragma unroll
    for (int ni = 0; ni < 4; ni++)
#pragma unroll
        for (int j = 0; j < 4; j++) acc_o[ni][j] = 0.0f;

    for (int kt = 0; kt < 32; kt++) {
        const int s = kt & 1;
#pragma unroll
        for (int i = 0; i < 4; i++) {
            store_split4(kr[i], sm + A_KH(s), sm + A_KL(s), (lr + i * 16) * 128 + lc * 8);
            store_split4(vr[i], sm + A_VH(s), sm + A_VL(s), (lr + i * 16) * 128 + lc * 8);
        }
        __syncthreads();
        if (kt < 31) {
            const float* Kt = Kb + (size_t)(kt + 1) * 64 * HD;
            const float* Vt = Vb + (size_t)(kt + 1) * 64 * HD;
#pragma unroll
            for (int i = 0; i < 4; i++) {
                kr[i] = *(const float4*)(Kt + (size_t)(lr + i * 16) * HD + lc * 4);
                vr[i] = *(const float4*)(Vt + (size_t)(lr + i * 16) * HD + lc * 4);
            }
        }

        // ---- S = Q K^T for this 64-k tile ----
        float acc_s[4][4];
#pragma unroll
        for (int ni = 0; ni < 4; ni++)
#pragma unroll
            for (int j = 0; j < 4; j++) acc_s[ni][j] = 0.0f;

#pragma unroll
        for (int kc = 0; kc < 4; kc++) {
            uint32_t ah[4], al[4];
            LDSM4(ah, swz(sb + A_QH, mw * 16 + (lane & 15), kc * 2 + (lane >> 4)));
            LDSM4(al, swz(sb + A_QL, mw * 16 + (lane & 15), kc * 2 + (lane >> 4)));
#pragma unroll
            for (int ni = 0; ni < 4; ni++) {
                uint32_t bh2[2], bl2[2];
                const int nb = nw * 32 + ni * 8 + (lane & 7);
                LDSM2(bh2, swz(sb + A_KH(s), nb, kc * 2 + ((lane >> 3) & 1)));
                LDSM2(bl2, swz(sb + A_KL(s), nb, kc * 2 + ((lane >> 3) & 1)));
                mma16816(acc_s[ni], ah, bh2);
                mma16816(acc_s[ni], ah, bl2);
                mma16816(acc_s[ni], al, bh2);
            }
        }

        // ---- epilogue: e = mask ? (p+1e-12)*2^(s*c) : 0 ; E global; e -> smem ----
        const size_t gr0 = ((size_t)(bh * SEQ + q0 + mw * 16 + fr)) * SEQ;
        const size_t cb  = (size_t)kt * 64 + nw * 32 + fc;
        const int    lcb = nw * 32 + fc;              // col within tile
#pragma unroll
        for (int ni = 0; ni < 4; ni++) {
            size_t g0 = gr0 + cb + ni * 8;
            int2   m0 = *(const int2*)  (Mk + g0);
            float2 p0 = *(const float2*)(P + g0);
            float2 e0;
            e0.x = m0.x ? (p0.x + 1e-12f) * fexp2(acc_s[ni][0] * EXSCL) : 0.0f;
            e0.y = m0.y ? (p0.y + 1e-12f) * fexp2(acc_s[ni][1] * EXSCL) : 0.0f;
            *(float2*)(E + g0) = e0;
            rs0 += e0.x + e0.y;
            size_t g1 = g0 + 8 * SEQ;
            int2   m1 = *(const int2*)  (Mk + g1);
            float2 p1 = *(const float2*)(P + g1);
            float2 e1;
            e1.x = m1.x ? (p1.x + 1e-12f) * fexp2(acc_s[ni][2] * EXSCL) : 0.0f;
            e1.y = m1.y ? (p1.y + 1e-12f) * fexp2(acc_s[ni][3] * EXSCL) : 0.0f;
            *(float2*)(E + g1) = e1;
            rs1 += e1.x + e1.y;
            // split into E smem tile (rows fr / fr+8 of warp's 16)
            const int off0 = (mw * 16 + fr) * 128 + (lcb + ni * 8) * 2;
            store_split2(e0.x, e0.y, sm + A_EH, sm + A_EL, off0);
            store_split2(e1.x, e1.y, sm + A_EH, sm + A_EL, off0 + 8 * 128);
        }
        __syncthreads();

        // ---- PV: O_acc += e_tile x V_tile ----
        const int vchk = lane >> 4;
#pragma unroll
        for (int kc = 0; kc < 4; kc++) {
            uint32_t bhf[2][4], blf[2][4];
#pragma unroll
            for (int ni2 = 0; ni2 < 2; ni2++) {
                const int nch = nw * 4 + ni2 * 2 + vchk;
                LDSM4T(bhf[ni2], swz(sb + A_VH(s), kc * 16 + (lane & 15), nch));
                LDSM4T(blf[ni2], swz(sb + A_VL(s), kc * 16 + (lane & 15), nch));
            }
            uint32_t ah[4], al[4];
            LDSM4(ah, swz(sb + A_EH, mw * 16 + (lane & 15), kc * 2 + (lane >> 4)));
            LDSM4(al, swz(sb + A_EL, mw * 16 + (lane & 15), kc * 2 + (lane >> 4)));
#pragma unroll
            for (int ni2 = 0; ni2 < 2; ni2++) {
                mma16816(acc_o[2 * ni2],     ah, bhf[ni2]);
                mma16816(acc_o[2 * ni2],     ah, blf[ni2]);
                mma16816(acc_o[2 * ni2],     al, bhf[ni2]);
                mma16816(acc_o[2 * ni2 + 1], ah, bhf[ni2] + 2);
                mma16816(acc_o[2 * ni2 + 1], ah, blf[ni2] + 2);
                mma16816(acc_o[2 * ni2 + 1], al, bhf[ni2] + 2);
            }
        }
    }

    // ---- rowsums -> global (for norm_k) + inv for O epilogue ----
    rs0 += __shfl_xor_sync(0xffffffffu, rs0, 1);
    rs0 += __shfl_xor_sync(0xffffffffu, rs0, 2);
    rs1 += __shfl_xor_sync(0xffffffffu, rs1, 1);
    rs1 += __shfl_xor_sync(0xffffffffu, rs1, 2);
    float* rss = (float*)(sm + A_RS);
    if ((lane & 3) == 0) {
        rss[nw * 64 + mw * 16 + fr]     = rs0;
        rss[nw * 64 + mw * 16 + fr + 8] = rs1;
    }
    __syncthreads();
    if (t < 64) {
        float sum = rss[t] + rss[64 + t];
        g_rowsum[bh * SEQ + q0 + t] = sum;
        rss[128 + t] = 1.0f / sum;
    }
    __syncthreads();

    // ---- O epilogue: scale by inv, write ----
    const int r0 = mw * 16 + (lane >> 2);
    const float i0 = rss[128 + r0], i1 = rss[128 + r0 + 8];
    const int c0 = nw * 32 + 2 * (lane & 3);
#pragma unroll
    for (int ni = 0; ni < 4; ni++) {
        size_t g0 = ((size_t)(bh * SEQ + q0 + r0)) * HD + c0 + ni * 8;
        *(float2*)(O + g0) = make_float2(acc_o[ni][0] * i0, acc_o[ni][1] * i0);
        *(float2*)(O + g0 + 8 * HD) = make_float2(acc_o[ni][2] * i1, acc_o[ni][3] * i1);
    }
}

// ---------------- norm_k: p_attn = E / rowsum (in place), proven 77us --------
__global__ void __launch_bounds__(256) norm_k(float* __restrict__ E)
{
    const int row = blockIdx.x;             // 0..32767
    const float inv = 1.0f / g_rowsum[row];
    float4* p = (float4*)(E + (size_t)row * SEQ);
    const int i = threadIdx.x;
    float4 v0 = p[i];
    v0.x *= inv; v0.y *= inv; v0.z *= inv; v0.w *= inv;
    p[i] = v0;
    float4 v1 = p[i + 256];
    v1.x *= inv; v1.y *= inv; v1.z *= inv; v1.w *= inv;
    p[i + 256] = v1;
}

extern "C" void kernel_launch(void* const* d_in, const int* in_sizes, int n_in,
                              void* d_out, int out_size) {
    const float* Q = (const float*)d_in[0];
    const float* K = (const float*)d_in[1];
    const float* V = (const float*)d_in[2];
    const int*   M = (const int*)  d_in[3];
    const float* P = (const float*)d_in[4];
    float* out = (float*)d_out;
    float* E   = out + OUT_ELEMS;

    cudaFuncSetAttribute(attn_k, cudaFuncAttributeMaxDynamicSharedMemorySize, A_SZ);

    attn_k<<<dim3(32, 16), 256, A_SZ>>>(Q, K, V, M, P, E, out);
    norm_k<<<16 * SEQ, 256>>>(E);
}

// round 15
// speedup vs baseline: 1.3148x; 1.3148x over previous
#include <cuda_runtime.h>
#include <cuda_bf16.h>
#include <cstdint>

#define SEQ 2048
#define HD  64
#define OUT_ELEMS (16*SEQ*HD)

__device__ float g_rowsum[16 * SEQ];

// ---------------- helpers ----------------
__device__ __forceinline__ uint32_t smem_u32(const void* p) {
    uint32_t a;
    asm("{ .reg .u64 t; cvta.to.shared.u64 t, %1; cvt.u32.u64 %0, t; }" : "=r"(a) : "l"(p));
    return a;
}

#define LDSM4(r, a) \
    asm volatile("ldmatrix.sync.aligned.m8n8.x4.shared.b16 {%0,%1,%2,%3}, [%4];" \
        : "=r"((r)[0]), "=r"((r)[1]), "=r"((r)[2]), "=r"((r)[3]) : "r"(a))
#define LDSM2(r, a) \
    asm volatile("ldmatrix.sync.aligned.m8n8.x2.shared.b16 {%0,%1}, [%2];" \
        : "=r"((r)[0]), "=r"((r)[1]) : "r"(a))
#define LDSM4T(r, a) \
    asm volatile("ldmatrix.sync.aligned.m8n8.x4.trans.shared.b16 {%0,%1,%2,%3}, [%4];" \
        : "=r"((r)[0]), "=r"((r)[1]), "=r"((r)[2]), "=r"((r)[3]) : "r"(a))

__device__ __forceinline__ void mma16816(float* d, const uint32_t* a, const uint32_t* b) {
    asm volatile(
        "mma.sync.aligned.m16n8k16.row.col.f32.bf16.bf16.f32 "
        "{%0,%1,%2,%3}, {%4,%5,%6,%7}, {%8,%9}, {%0,%1,%2,%3};"
        : "+f"(d[0]), "+f"(d[1]), "+f"(d[2]), "+f"(d[3])
        : "r"(a[0]), "r"(a[1]), "r"(a[2]), "r"(a[3]), "r"(b[0]), "r"(b[1]));
}

// fast 2^t : FFMA-only. |t| < 60 assumed.
__device__ __forceinline__ float fexp2(float t) {
    float z = t + 12582912.0f;
    int   i = __float_as_int(z);
    float f = t - (z - 12582912.0f);
    float p =          1.33335581e-3f;
    p = fmaf(p, f, 9.61812910e-3f);
    p = fmaf(p, f, 5.55041087e-2f);
    p = fmaf(p, f, 2.40226507e-1f);
    p = fmaf(p, f, 6.93147180e-1f);
    p = fmaf(p, f, 1.0f);
    float sc = __int_as_float((i + 127) << 23);
    return p * sc;
}
#define EXSCL 0.18033688011f   // 0.125 * log2(e)

// bf16 tiles: 64 elems (128B) per row, 16B-chunk xor swizzle
#define SW(o) ((o) ^ (((o) >> 3) & 0x70))
__device__ __forceinline__ uint32_t swz(uint32_t base, int row, int chunk) {
    return base + row * 128 + (((chunk ^ (row & 7)) & 7) << 4);
}

// split f32x4 -> bf16 hi/lo, 2x STS.64 (off % 8 == 0 so SW(off+4)==SW(off)+4)
__device__ __forceinline__ void store_split4(float4 v, char* hb, char* lb, int off) {
    __nv_bfloat162 h0 = __floats2bfloat162_rn(v.x, v.y);
    __nv_bfloat162 h1 = __floats2bfloat162_rn(v.z, v.w);
    float2 f0 = __bfloat1622float2(h0), f1 = __bfloat1622float2(h1);
    __nv_bfloat162 l0 = __floats2bfloat162_rn(v.x - f0.x, v.y - f0.y);
    __nv_bfloat162 l1 = __floats2bfloat162_rn(v.z - f1.x, v.w - f1.y);
    int s0 = SW(off);
    uint2 hp = make_uint2(reinterpret_cast<uint32_t&>(h0), reinterpret_cast<uint32_t&>(h1));
    uint2 lp = make_uint2(reinterpret_cast<uint32_t&>(l0), reinterpret_cast<uint32_t&>(l1));
    *(uint2*)(hb + s0) = hp;
    *(uint2*)(lb + s0) = lp;
}

// ------------------- Kernel A: S=QK^T, exp epilogue, rowsum -------------------
// 64-row q-tiles x 64-wide k-tiles, double-buffered K, register prefetch of K
// AND of mask/p (hidden under the MMA block). Direct fragment epilogue.
// smem: QH 8K | QL 8K | K stages 2x16K | rs
#define S_QH 0
#define S_QL 8192
#define S_KH(s) (16384 + (s)*16384)
#define S_KL(s) (16384 + (s)*16384 + 8192)
#define S_RS 49152
#define S_SZ (S_RS + 768)

__global__ void __launch_bounds__(256, 2) scores_k(
    const float* __restrict__ Q, const float* __restrict__ Kg,
    const int* __restrict__ Mk, const float* __restrict__ P, float* __restrict__ E)
{
    extern __shared__ char sm[];
    const uint32_t sb = smem_u32(sm);
    const int t = threadIdx.x, w = t >> 5, lane = t & 31;
    const int mw = w >> 1, nw = w & 1;     // warp tile: rows mw*16, cols nw*32
    const int bh = blockIdx.y, q0 = blockIdx.x * 64;

    const float* Qb = Q + ((size_t)bh * SEQ + q0) * HD;
    const float* Kb = Kg + (size_t)bh * SEQ * HD;

    // resident Q (64 x 64) split to smem
#pragma unroll
    for (int i = 0; i < 4; i++) {
        int idx = t + i * 256, r = idx >> 4, c = idx & 15;
        store_split4(*(const float4*)(Qb + r * HD + c * 4), sm + S_QH, sm + S_QL, r * 128 + c * 8);
    }

    // prefetch K tile 0 (64 rows x 64 cols)
    const int lr = t >> 4, lc = t & 15;
    float4 kr[4];
#pragma unroll
    for (int i = 0; i < 4; i++)
        kr[i] = *(const float4*)(Kb + (size_t)(lr + i * 16) * HD + lc * 4);

    float rs0 = 0.0f, rs1 = 0.0f;
    const int fr = lane >> 2;
    const int fc = 2 * (lane & 3);
    const size_t gr0 = ((size_t)(bh * SEQ + q0 + mw * 16 + fr)) * SEQ;
    const size_t gr1 = gr0 + 8 * SEQ;

    for (int kt = 0; kt < 32; kt++) {
        const int s = kt & 1;
#pragma unroll
        for (int i = 0; i < 4; i++)
            store_split4(kr[i], sm + S_KH(s), sm + S_KL(s), (lr + i * 16) * 128 + lc * 8);
        __syncthreads();
        if (kt < 31) {
            const float* Kt = Kb + (size_t)(kt + 1) * 64 * HD;
#pragma unroll
            for (int i = 0; i < 4; i++)
                kr[i] = *(const float4*)(Kt + (size_t)(lr + i * 16) * HD + lc * 4);
        }

        // prefetch mask/p for THIS tile (consumed after MMA; latency hidden)
        const size_t cb = (size_t)kt * 64 + nw * 32 + fc;
        int2   m0[4], m1[4];
        float2 pp0[4], pp1[4];
#pragma unroll
        for (int ni = 0; ni < 4; ni++) {
            size_t g0 = gr0 + cb + ni * 8;
            m0[ni]  = *(const int2*)  (Mk + g0);
            pp0[ni] = *(const float2*)(P + g0);
            size_t g1 = gr1 + cb + ni * 8;
            m1[ni]  = *(const int2*)  (Mk + g1);
            pp1[ni] = *(const float2*)(P + g1);
        }

        // ---- S = Q K^T for this 64-k tile ----
        float acc[4][4];
#pragma unroll
        for (int ni = 0; ni < 4; ni++)
#pragma unroll
            for (int j = 0; j < 4; j++) acc[ni][j] = 0.0f;

#pragma unroll
        for (int kc = 0; kc < 4; kc++) {
            uint32_t ah[4], al[4];
            LDSM4(ah, swz(sb + S_QH, mw * 16 + (lane & 15), kc * 2 + (lane >> 4)));
            LDSM4(al, swz(sb + S_QL, mw * 16 + (lane & 15), kc * 2 + (lane >> 4)));
#pragma unroll
            for (int ni = 0; ni < 4; ni++) {
                uint32_t bh2[2], bl2[2];
                const int nb = nw * 32 + ni * 8 + (lane & 7);
                LDSM2(bh2, swz(sb + S_KH(s), nb, kc * 2 + ((lane >> 3) & 1)));
                LDSM2(bl2, swz(sb + S_KL(s), nb, kc * 2 + ((lane >> 3) & 1)));
                mma16816(acc[ni], ah, bh2);
                mma16816(acc[ni], ah, bl2);
                mma16816(acc[ni], al, bh2);
            }
        }

        // ---- epilogue: pure register compute + stores ----
#pragma unroll
        for (int ni = 0; ni < 4; ni++) {
            float2 e0;
            e0.x = m0[ni].x ? (pp0[ni].x + 1e-12f) * fexp2(acc[ni][0] * EXSCL) : 0.0f;
            e0.y = m0[ni].y ? (pp0[ni].y + 1e-12f) * fexp2(acc[ni][1] * EXSCL) : 0.0f;
            *(float2*)(E + gr0 + cb + ni * 8) = e0;
            rs0 += e0.x + e0.y;
            float2 e1;
            e1.x = m1[ni].x ? (pp1[ni].x + 1e-12f) * fexp2(acc[ni][2] * EXSCL) : 0.0f;
            e1.y = m1[ni].y ? (pp1[ni].y + 1e-12f) * fexp2(acc[ni][3] * EXSCL) : 0.0f;
            *(float2*)(E + gr1 + cb + ni * 8) = e1;
            rs1 += e1.x + e1.y;
        }
    }

    rs0 += __shfl_xor_sync(0xffffffffu, rs0, 1);
    rs0 += __shfl_xor_sync(0xffffffffu, rs0, 2);
    rs1 += __shfl_xor_sync(0xffffffffu, rs1, 1);
    rs1 += __shfl_xor_sync(0xffffffffu, rs1, 2);
    float* rss = (float*)(sm + S_RS);
    if ((lane & 3) == 0) {
        rss[nw * 64 + mw * 16 + fr]     = rs0;
        rss[nw * 64 + mw * 16 + fr + 8] = rs1;
    }
    __syncthreads();
    if (t < 64) g_rowsum[bh * SEQ + q0 + t] = rss[t] + rss[64 + t];
}

// --------------- Kernel B: normalize E in place + O = p_attn V ---------------
// (R12 variant, measured 122.6us — unchanged)
#define B_EH(s) ((s)*32768)
#define B_EL(s) ((s)*32768 + 8192)
#define B_VH(s) ((s)*32768 + 16384)
#define B_VL(s) ((s)*32768 + 24576)
#define B_IV 65536
#define B_SZ (B_IV + 256)

__global__ void __launch_bounds__(256, 2) pv_k(
    const float* __restrict__ Vg, float* __restrict__ E, float* __restrict__ O)
{
    extern __shared__ char sm[];
    const uint32_t sb = smem_u32(sm);
    const int t = threadIdx.x, w = t >> 5, lane = t & 31;
    const int mw = w >> 1, nw = w & 1;
    const int bh = blockIdx.y, q0 = blockIdx.x * 64;

    float* sinv = (float*)(sm + B_IV);
    if (t < 64) sinv[t] = 1.0f / g_rowsum[bh * SEQ + q0 + t];

    float* Eb = E + ((size_t)bh * SEQ + q0) * SEQ;
    const float* Vb = Vg + (size_t)bh * SEQ * HD;

    const int r_ = t >> 4, c_ = t & 15;

    float4 er[4], vr[4];
#pragma unroll
    for (int i = 0; i < 4; i++) {
        er[i] = *(const float4*)(Eb + (size_t)(r_ + i * 16) * SEQ + c_ * 4);
        vr[i] = *(const float4*)(Vb + (size_t)(r_ + i * 16) * HD + c_ * 4);
    }

    float acc[4][4];
#pragma unroll
    for (int ni = 0; ni < 4; ni++)
#pragma unroll
        for (int j = 0; j < 4; j++) acc[ni][j] = 0.0f;

    __syncthreads();

    for (int kt = 0; kt < 32; kt++) {
        const int s = kt & 1;
#pragma unroll
        for (int i = 0; i < 4; i++) {
            const int r = r_ + i * 16;
            const float inv = sinv[r];
            float4 v = er[i];
            v.x *= inv; v.y *= inv; v.z *= inv; v.w *= inv;
            *(float4*)(Eb + (size_t)r * SEQ + kt * 64 + c_ * 4) = v;
            store_split4(v, sm + B_EH(s), sm + B_EL(s), r * 128 + c_ * 8);
            store_split4(vr[i], sm + B_VH(s), sm + B_VL(s), r * 128 + c_ * 8);
        }
        __syncthreads();
        if (kt < 31) {
#pragma unroll
            for (int i = 0; i < 4; i++) {
                er[i] = *(const float4*)(Eb + (size_t)(r_ + i * 16) * SEQ + (kt + 1) * 64 + c_ * 4);
                vr[i] = *(const float4*)(Vb + (size_t)((kt + 1) * 64 + r_ + i * 16) * HD + c_ * 4);
            }
        }
        const int vchk_off = lane >> 4;
#pragma unroll
        for (int kc = 0; kc < 4; kc++) {
            uint32_t bhf[2][4], blf[2][4];
#pragma unroll
            for (int ni2 = 0; ni2 < 2; ni2++) {
                const int nch = nw * 4 + ni2 * 2 + vchk_off;
                LDSM4T(bhf[ni2], swz(sb + B_VH(s), kc * 16 + (lane & 15), nch));
                LDSM4T(blf[ni2], swz(sb + B_VL(s), kc * 16 + (lane & 15), nch));
            }
            uint32_t ah[4], al[4];
            LDSM4(ah, swz(sb + B_EH(s), mw * 16 + (lane & 15), kc * 2 + (lane >> 4)));
            LDSM4(al, swz(sb + B_EL(s), mw * 16 + (lane & 15), kc * 2 + (lane >> 4)));
#pragma unroll
            for (int ni2 = 0; ni2 < 2; ni2++) {
                mma16816(acc[2 * ni2],     ah, bhf[ni2]);
                mma16816(acc[2 * ni2],     ah, blf[ni2]);
                mma16816(acc[2 * ni2],     al, bhf[ni2]);
                mma16816(acc[2 * ni2 + 1], ah, bhf[ni2] + 2);
                mma16816(acc[2 * ni2 + 1], ah, blf[ni2] + 2);
                mma16816(acc[2 * ni2 + 1], al, bhf[ni2] + 2);
            }
        }
    }

    const int r0 = mw * 16 + (lane >> 2);
    const int c0 = nw * 32 + 2 * (lane & 3);
#pragma unroll
    for (int ni = 0; ni < 4; ni++) {
        size_t g0 = ((size_t)(bh * SEQ + q0 + r0)) * HD + c0 + ni * 8;
        *(float2*)(O + g0) = make_float2(acc[ni][0], acc[ni][1]);
        *(float2*)(O + g0 + 8 * HD) = make_float2(acc[ni][2], acc[ni][3]);
    }
}

extern "C" void kernel_launch(void* const* d_in, const int* in_sizes, int n_in,
                              void* d_out, int out_size) {
    const float* Q = (const float*)d_in[0];
    const float* K = (const float*)d_in[1];
    const float* V = (const float*)d_in[2];
    const int*   M = (const int*)  d_in[3];
    const float* P = (const float*)d_in[4];
    float* out = (float*)d_out;
    float* E   = out + OUT_ELEMS;

    cudaFuncSetAttribute(scores_k, cudaFuncAttributeMaxDynamicSharedMemorySize, S_SZ);
    cudaFuncSetAttribute(pv_k,     cudaFuncAttributeMaxDynamicSharedMemorySize, B_SZ);

    scores_k<<<dim3(32, 16), 256, S_SZ>>>(Q, K, M, P, E);
    pv_k<<<dim3(32, 16), 256, B_SZ>>>(V, E, out);
}